// round 14
// baseline (speedup 1.0000x reference)
#include <cuda_runtime.h>
#include <cuda_fp16.h>
#include <math.h>

namespace {
constexpr int Bsz  = 8;
constexpr int Lsz  = 1024;
constexpr int Hsz  = 8;
constexpr int Esz  = 64;
constexpr int HIST = 512;
constexpr float SCL2 = 0.125f * 1.4426950408889634f;  // 1/sqrt(E) * log2(e)
constexpr int BM = 128;            // q rows per phase
constexpr int BN = 64;             // key tile
constexpr int SKH = 72;            // smem row stride (halves); 144B pitch
constexpr int STG_K = BN * SKH;    // 4608 halves: K part of a stage
constexpr int STG   = 2 * STG_K;   // 9216 halves per stage (K + V)
constexpr int SM_Q  = BM * SKH;    // dedicated Q region (halves)
constexpr int SMEM_BYTES = (3 * STG + SM_Q) * 2 + 2 * BM * 4;  // 74,752 B
constexpr unsigned ONES2 = 0x3C003C00u;               // half2(1,1)
}

// fp16 K/V scratch, head-major [b,h,l,e] so tiles are contiguous
__device__ __half g_Kh[Bsz * Hsz * Lsz * Esz];
__device__ __half g_Vh[Bsz * Hsz * Lsz * Esz];

__device__ __forceinline__ void ldsm4(unsigned* r, unsigned a) {
    asm volatile("ldmatrix.sync.aligned.m8n8.x4.shared.b16 {%0,%1,%2,%3}, [%4];"
        : "=r"(r[0]), "=r"(r[1]), "=r"(r[2]), "=r"(r[3]) : "r"(a));
}
__device__ __forceinline__ void ldsm4t(unsigned* r, unsigned a) {
    asm volatile("ldmatrix.sync.aligned.m8n8.x4.trans.shared.b16 {%0,%1,%2,%3}, [%4];"
        : "=r"(r[0]), "=r"(r[1]), "=r"(r[2]), "=r"(r[3]) : "r"(a));
}
__device__ __forceinline__ void mma16816(float* d, const unsigned* a, unsigned b0, unsigned b1) {
    asm("mma.sync.aligned.m16n8k16.row.col.f32.f16.f16.f32 "
        "{%0,%1,%2,%3},{%4,%5,%6,%7},{%8,%9},{%0,%1,%2,%3};"
        : "+f"(d[0]), "+f"(d[1]), "+f"(d[2]), "+f"(d[3])
        : "r"(a[0]), "r"(a[1]), "r"(a[2]), "r"(a[3]), "r"(b0), "r"(b1));
}
__device__ __forceinline__ unsigned packh2(float x, float y) {
    __half2 h = __floats2half2_rn(x, y);
    return *reinterpret_cast<unsigned*>(&h);
}
__device__ __forceinline__ unsigned ex2h2(unsigned x) {
    unsigned r; asm("ex2.approx.f16x2 %0, %1;" : "=r"(r) : "r"(x)); return r;
}
__device__ __forceinline__ float h2lo(unsigned u) {
    __half2 h = *reinterpret_cast<__half2*>(&u); return __low2float(h);
}
__device__ __forceinline__ float h2hi(unsigned u) {
    __half2 h = *reinterpret_cast<__half2*>(&u); return __high2float(h);
}
__device__ __forceinline__ void cp16(unsigned sm, const void* gp) {
    asm volatile("cp.async.cg.shared.global [%0], [%1], 16;" :: "r"(sm), "l"(gp));
}

// ---- prepass: fp32 [b,l,h,e] -> fp16 [b,h,l,e] for K and V ----
__global__ __launch_bounds__(256)
void convert_kv_kernel(const float* __restrict__ K, const float* __restrict__ V)
{
    const int idx = blockIdx.x * 256 + threadIdx.x;   // float4 units
    const int e4 = idx & 15;
    const int h  = (idx >> 4) & 7;
    const int bl = idx >> 7;                          // b*1024 + l
    const int b  = bl >> 10;
    const int l  = bl & 1023;
    const float4 k4 = reinterpret_cast<const float4*>(K)[idx];
    const float4 v4 = reinterpret_cast<const float4*>(V)[idx];
    const int out = (((b * 8 + h) * 1024) + l) * 16 + e4;   // uint2 units
    reinterpret_cast<uint2*>(g_Kh)[out] = make_uint2(packh2(k4.x, k4.y), packh2(k4.z, k4.w));
    reinterpret_cast<uint2*>(g_Vh)[out] = make_uint2(packh2(v4.x, v4.y), packh2(v4.z, v4.w));
}

__global__ __launch_bounds__(256, 2)
void fftcc_attn_kernel(const float* __restrict__ Q,  const float* __restrict__ V,
                       const float* __restrict__ QD, const float* __restrict__ KD,
                       const float* __restrict__ VD, float* __restrict__ Out)
{
    extern __shared__ __half smh[];
    __half* Qh  = smh + 3 * STG;                       // dedicated Q region
    float* dSs = (float*)(smh + 3 * STG + SM_Q);       // [BM] diag scores
    float* pdS = dSs + BM;                             // [BM] diag probabilities

    unsigned st_u[3];
    #pragma unroll
    for (int s = 0; s < 3; ++s)
        st_u[s] = (unsigned)__cvta_generic_to_shared(smh + s * STG);
    const unsigned qs_u = (unsigned)__cvta_generic_to_shared(Qh);

    const int bh = blockIdx.y;
    const int b  = bh >> 3;
    const int h  = bh & 7;
    const int tid  = threadIdx.x;
    const int w    = tid >> 5;
    const int lane = tid & 31;
    const int rr   = lane >> 2;
    const int qi   = lane & 3;
    const int rs   = Hsz * Esz;          // 512
    const int base = (b * Lsz * Hsz + h) * Esz;
    const int wb = w * 16;

    const __half* kvK = g_Kh + (size_t)(b * 8 + h) * Lsz * Esz;
    const __half* kvV = g_Vh + (size_t)(b * 8 + h) * Lsz * Esz;

    // ldmatrix lane addressing
    const int g  = lane >> 3, r8 = lane & 7;
    const unsigned qa_base = qs_u +
        (unsigned)(((wb + ((g & 1) << 3) + r8) * SKH + ((g >> 1) << 3)) * 2);
    const unsigned kf_off = (unsigned)(((((g >> 1) << 3) + r8) * SKH + ((g & 1) << 3)) * 2);
    const unsigned vf_off = (unsigned)(((((g & 1) << 3) + r8) * SKH + ((g >> 1) << 3)) * 2);

    // cp.async per-thread chunk mapping
    const int cp_row[2] = { tid >> 3, (256 + tid) >> 3 };        // rows 0..63
    const int cp_c8    = (tid & 7) * 8;

    // Perfectly balanced pairing: heavy tile (7-x) then light tile (x);
    // every block does (16-2x) + (2x+2) = 18 tile-units. 256 blocks = 1 wave.
    const int x = blockIdx.x;            // 0..3
    const int m0s[2] = { (7 - x) * BM, x * BM };

    #pragma unroll 1
    for (int phase = 0; phase < 2; ++phase) {
        const int m0 = m0s[phase];
        const bool has_diag = (m0 >= HIST);   // phase 0: true, phase 1: false

        // ---- Load Q (q_eff), pre-scaled by SCL2, fp16 ----
        #pragma unroll
        for (int it = 0; it < 8; ++it) {
            const int idx = it * 256 + tid;
            const int r  = idx >> 4;
            const int ce = idx & 15;
            const int l  = m0 + r;
            const float* src = (l < HIST) ? Q : QD;
            const float4 v = *reinterpret_cast<const float4*>(src + base + l * rs + (ce << 2));
            *reinterpret_cast<uint2*>(Qh + r * SKH + (ce << 2)) =
                make_uint2(packh2(v.x * SCL2, v.y * SCL2), packh2(v.z * SCL2, v.w * SCL2));
        }
        // ---- Diagonal raw scores (full fp32, pre-scaled) ----
        if (has_diag && tid < BM) {
            const int l = m0 + tid;
            const float* qr = QD + base + l * rs;
            const float* kr = KD + base + l * rs;
            float acc = 0.f;
            #pragma unroll
            for (int ce = 0; ce < 16; ++ce) {
                const float4 qv = *reinterpret_cast<const float4*>(qr + (ce << 2));
                const float4 kv = *reinterpret_cast<const float4*>(kr + (ce << 2));
                acc += qv.x * kv.x + qv.y * kv.y + qv.z * kv.z + qv.w * kv.w;
            }
            dSs[tid] = acc * SCL2;
        }

        const int ntiles = (m0 >> 6) + 2;

        // ---- prologue: issue cp.async for tiles 0 and 1 (stages 0, 1) ----
        #pragma unroll
        for (int t0 = 0; t0 < 2; ++t0) {
            const unsigned sb = st_u[t0];
            #pragma unroll
            for (int it = 0; it < 2; ++it) {
                const int row = cp_row[it];
                const unsigned so = (unsigned)((row * SKH + cp_c8) * 2);
                const int go = (t0 * 64 + row) * Esz + cp_c8;
                cp16(sb + so,        kvK + go);
                cp16(sb + 9216 + so, kvV + go);
            }
            asm volatile("cp.async.commit_group;" ::: "memory");
        }
        __syncthreads();                      // Q + dSs visible

        // ---- Q A-fragments (persistent for this phase; 16 regs) ----
        unsigned qa[4][4];
        #pragma unroll
        for (int kb = 0; kb < 4; ++kb) ldsm4(qa[kb], qa_base + kb * 32);

        float o[8][4];
        #pragma unroll
        for (int nf = 0; nf < 8; ++nf)
            #pragma unroll
            for (int c = 0; c < 4; ++c) o[nf][c] = 0.f;
        float lsum0 = 0.f, lsum1 = 0.f;       // no-max softmax: P = 2^S

        const int l0 = m0 + wb + rr;
        const int l1 = l0 + 8;

        int stg = 0;
        for (int t = 0; t < ntiles; ++t) {
            asm volatile("cp.async.wait_group 1;" ::: "memory");
            __syncthreads();                  // tile t's stage visible; t-1 fully read

            // ---- issue cp.async for tile t+2 EARLY ----
            if (t + 2 < ntiles) {
                const int s2 = (stg + 2 >= 3) ? stg - 1 : stg + 2;
                const unsigned sb = st_u[s2];
                const int n2 = (t + 2) << 6;
                #pragma unroll
                for (int it = 0; it < 2; ++it) {
                    const int row = cp_row[it];
                    const unsigned so = (unsigned)((row * SKH + cp_c8) * 2);
                    const int go = (n2 + row) * Esz + cp_c8;
                    cp16(sb + so,        kvK + go);
                    cp16(sb + 9216 + so, kvV + go);
                }
            }
            asm volatile("cp.async.commit_group;" ::: "memory");

            const unsigned ks_b = st_u[stg];
            const unsigned vs_b = st_u[stg] + 9216;
            const int n0 = t << 6;
            const bool crossing = (n0 >= m0);
            const bool active = (wb + 15 + m0) >= n0;

            if (active) {
                // ---- S = Q @ K^T ----
                float s[8][4];
                #pragma unroll
                for (int nf = 0; nf < 8; ++nf)
                    #pragma unroll
                    for (int c = 0; c < 4; ++c) s[nf][c] = 0.f;
                #pragma unroll
                for (int kb = 0; kb < 4; ++kb) {
                    #pragma unroll
                    for (int nb = 0; nb < 4; ++nb) {
                        unsigned bb[4];
                        ldsm4(bb, ks_b + kf_off + (unsigned)((nb * 16 * SKH + kb * 16) * 2));
                        mma16816(s[2 * nb],     qa[kb], bb[0], bb[1]);
                        mma16816(s[2 * nb + 1], qa[kb], bb[2], bb[3]);
                    }
                }

                // ---- diag substitution + causal mask ----
                if (crossing) {
                    #pragma unroll
                    for (int nf = 0; nf < 8; ++nf) {
                        const int col = n0 + nf * 8 + 2 * qi;
                        if (has_diag) {
                            if (col     == l0) s[nf][0] = dSs[l0 - m0];
                            if (col + 1 == l0) s[nf][1] = dSs[l0 - m0];
                            if (col     == l1) s[nf][2] = dSs[l1 - m0];
                            if (col + 1 == l1) s[nf][3] = dSs[l1 - m0];
                        }
                        if (col     > l0) s[nf][0] = -INFINITY;
                        if (col + 1 > l0) s[nf][1] = -INFINITY;
                        if (col     > l1) s[nf][2] = -INFINITY;
                        if (col + 1 > l1) s[nf][3] = -INFINITY;
                    }
                }

                // ---- P = 2^S, packed ----
                unsigned ph[8][2];
                #pragma unroll
                for (int nf = 0; nf < 8; ++nf) {
                    ph[nf][0] = ex2h2(packh2(s[nf][0], s[nf][1]));
                    ph[nf][1] = ex2h2(packh2(s[nf][2], s[nf][3]));
                }

                // ---- capture diag probabilities (unnormalized) ----
                if (crossing && has_diag) {
                    #pragma unroll
                    for (int nf = 0; nf < 8; ++nf) {
                        const int col = n0 + nf * 8 + 2 * qi;
                        if (col     == l0) pdS[l0 - m0] = h2lo(ph[nf][0]);
                        if (col + 1 == l0) pdS[l0 - m0] = h2hi(ph[nf][0]);
                        if (col     == l1) pdS[l1 - m0] = h2lo(ph[nf][1]);
                        if (col + 1 == l1) pdS[l1 - m0] = h2hi(ph[nf][1]);
                    }
                }

                // ---- O += P @ V ; row sums via P @ ones ----
                float ssum[4] = {0.f, 0.f, 0.f, 0.f};
                #pragma unroll
                for (int kb = 0; kb < 4; ++kb) {
                    unsigned pa[4];
                    pa[0] = ph[2 * kb][0];
                    pa[1] = ph[2 * kb][1];
                    pa[2] = ph[2 * kb + 1][0];
                    pa[3] = ph[2 * kb + 1][1];
                    mma16816(ssum, pa, ONES2, ONES2);
                    #pragma unroll
                    for (int nb = 0; nb < 4; ++nb) {
                        unsigned bb[4];
                        ldsm4t(bb, vs_b + vf_off + (unsigned)((kb * 16 * SKH + nb * 16) * 2));
                        mma16816(o[2 * nb],     pa, bb[0], bb[1]);
                        mma16816(o[2 * nb + 1], pa, bb[2], bb[3]);
                    }
                }
                lsum0 += ssum[0];
                lsum1 += ssum[2];
            }

            stg = (stg + 1 == 3) ? 0 : stg + 1;
        }

        // ---- epilogue: diag value substitution, normalize, store ----
        __syncwarp();                        // pdS written by sibling lanes
        const float inv0 = 1.0f / lsum0;
        const float inv1 = 1.0f / lsum1;
        const float pd0 = has_diag ? pdS[l0 - m0] : 0.f;
        const float pd1 = has_diag ? pdS[l1 - m0] : 0.f;

        #pragma unroll
        for (int nf = 0; nf < 8; ++nf) {
            const int e = nf * 8 + 2 * qi;
            float v00 = o[nf][0], v01 = o[nf][1], v10 = o[nf][2], v11 = o[nf][3];
            if (has_diag) {
                const float2 vd0 = *reinterpret_cast<const float2*>(VD + base + l0 * rs + e);
                const float2 vo0 = *reinterpret_cast<const float2*>(V  + base + l0 * rs + e);
                const float2 vd1 = *reinterpret_cast<const float2*>(VD + base + l1 * rs + e);
                const float2 vo1 = *reinterpret_cast<const float2*>(V  + base + l1 * rs + e);
                v00 += pd0 * (vd0.x - vo0.x);
                v01 += pd0 * (vd0.y - vo0.y);
                v10 += pd1 * (vd1.x - vo1.x);
                v11 += pd1 * (vd1.y - vo1.y);
            }
            *reinterpret_cast<float2*>(Out + base + l0 * rs + e) = make_float2(v00 * inv0, v01 * inv0);
            *reinterpret_cast<float2*>(Out + base + l1 * rs + e) = make_float2(v10 * inv1, v11 * inv1);
        }

        // ---- phase transition: drain ring, then safe to restage Q/dSs ----
        if (phase == 0) {
            asm volatile("cp.async.wait_group 0;" ::: "memory");
            __syncthreads();
        }
    }
}

extern "C" void kernel_launch(void* const* d_in, const int* in_sizes, int n_in,
                              void* d_out, int out_size)
{
    const float* Q  = (const float*)d_in[0];
    const float* K  = (const float*)d_in[1];
    const float* V  = (const float*)d_in[2];
    const float* QD = (const float*)d_in[3];
    const float* KD = (const float*)d_in[4];
    const float* VD = (const float*)d_in[5];
    float* Out = (float*)d_out;

    convert_kv_kernel<<<(Bsz * Lsz * Hsz * Esz / 4) / 256, 256>>>(K, V);

    cudaFuncSetAttribute(fftcc_attn_kernel,
                         cudaFuncAttributeMaxDynamicSharedMemorySize, SMEM_BYTES);
    dim3 grid(4, Bsz * Hsz);    // 256 blocks: one perfectly-balanced wave
    fftcc_attn_kernel<<<grid, 256, SMEM_BYTES>>>(Q, V, QD, KD, VD, Out);
}

// round 16
// speedup vs baseline: 1.2116x; 1.2116x over previous
#include <cuda_runtime.h>
#include <cuda_fp16.h>
#include <math.h>

namespace {
constexpr int Bsz  = 8;
constexpr int Lsz  = 1024;
constexpr int Hsz  = 8;
constexpr int Esz  = 64;
constexpr int HIST = 512;
constexpr float SCL2 = 0.125f * 1.4426950408889634f;  // 1/sqrt(E) * log2(e)
constexpr int BM = 128;            // q rows per phase
constexpr int BN = 64;             // key tile
constexpr int SKH = 72;            // smem row stride (halves); 144B pitch
constexpr int STG_K = BN * SKH;    // 4608 halves: K part of a stage
constexpr int STG   = 2 * STG_K;   // 9216 halves per stage (K + V)
constexpr int SM_Q  = BM * SKH;    // dedicated Q region (halves)
constexpr int SMEM_BYTES = (3 * STG + SM_Q) * 2 + 2 * BM * 4;  // 74,752 B
constexpr unsigned ONES2 = 0x3C003C00u;               // half2(1,1)
}

// fp16 K/V scratch, head-major [b,h,l,e] so tiles are contiguous
__device__ __half g_Kh[Bsz * Hsz * Lsz * Esz];
__device__ __half g_Vh[Bsz * Hsz * Lsz * Esz];
// per-head conversion arrival counter; +4 per launch (generation scheme, no reset)
__device__ unsigned g_count[Bsz * Hsz];

__device__ __forceinline__ void ldsm4(unsigned* r, unsigned a) {
    asm volatile("ldmatrix.sync.aligned.m8n8.x4.shared.b16 {%0,%1,%2,%3}, [%4];"
        : "=r"(r[0]), "=r"(r[1]), "=r"(r[2]), "=r"(r[3]) : "r"(a));
}
__device__ __forceinline__ void ldsm4t(unsigned* r, unsigned a) {
    asm volatile("ldmatrix.sync.aligned.m8n8.x4.trans.shared.b16 {%0,%1,%2,%3}, [%4];"
        : "=r"(r[0]), "=r"(r[1]), "=r"(r[2]), "=r"(r[3]) : "r"(a));
}
__device__ __forceinline__ void mma16816(float* d, const unsigned* a, unsigned b0, unsigned b1) {
    asm("mma.sync.aligned.m16n8k16.row.col.f32.f16.f16.f32 "
        "{%0,%1,%2,%3},{%4,%5,%6,%7},{%8,%9},{%0,%1,%2,%3};"
        : "+f"(d[0]), "+f"(d[1]), "+f"(d[2]), "+f"(d[3])
        : "r"(a[0]), "r"(a[1]), "r"(a[2]), "r"(a[3]), "r"(b0), "r"(b1));
}
__device__ __forceinline__ unsigned packh2(float x, float y) {
    __half2 h = __floats2half2_rn(x, y);
    return *reinterpret_cast<unsigned*>(&h);
}
__device__ __forceinline__ unsigned ex2h2(unsigned x) {
    unsigned r; asm("ex2.approx.f16x2 %0, %1;" : "=r"(r) : "r"(x)); return r;
}
__device__ __forceinline__ float h2lo(unsigned u) {
    __half2 h = *reinterpret_cast<__half2*>(&u); return __low2float(h);
}
__device__ __forceinline__ float h2hi(unsigned u) {
    __half2 h = *reinterpret_cast<__half2*>(&u); return __high2float(h);
}
__device__ __forceinline__ void cp16(unsigned sm, const void* gp) {
    asm volatile("cp.async.cg.shared.global [%0], [%1], 16;" :: "r"(sm), "l"(gp));
}

__global__ __launch_bounds__(256, 2)
void fftcc_attn_kernel(const float* __restrict__ Q,  const float* __restrict__ K,
                       const float* __restrict__ V,  const float* __restrict__ QD,
                       const float* __restrict__ KD, const float* __restrict__ VD,
                       float* __restrict__ Out)
{
    extern __shared__ __half smh[];
    __half* Qh  = smh + 3 * STG;                       // dedicated Q region
    float* dSs = (float*)(smh + 3 * STG + SM_Q);       // [BM] diag scores
    float* pdS = dSs + BM;                             // [BM] diag probabilities
    __shared__ unsigned s_target;                      // group-barrier target

    unsigned st_u[3];
    #pragma unroll
    for (int s = 0; s < 3; ++s)
        st_u[s] = (unsigned)__cvta_generic_to_shared(smh + s * STG);
    const unsigned qs_u = (unsigned)__cvta_generic_to_shared(Qh);

    const int bh = blockIdx.y;
    const int b  = bh >> 3;
    const int h  = bh & 7;
    const int tid  = threadIdx.x;
    const int w    = tid >> 5;
    const int lane = tid & 31;
    const int rr   = lane >> 2;
    const int qi   = lane & 3;
    const int rs   = Hsz * Esz;          // 512
    const int base = (b * Lsz * Hsz + h) * Esz;
    const int wb = w * 16;
    const int x = blockIdx.x;            // 0..3

    const __half* kvK = g_Kh + (size_t)bh * Lsz * Esz;
    const __half* kvV = g_Vh + (size_t)bh * Lsz * Esz;

    // ---- fused conversion: this block converts rows [256x, 256x+256) of head bh ----
    {
        const int lbase = x * 256;
        #pragma unroll
        for (int it = 0; it < 16; ++it) {
            const int idx = it * 256 + tid;          // 0..4095 float4-chunks
            const int l  = lbase + (idx >> 4);
            const int e4 = idx & 15;
            const int gi = base + l * rs + (e4 << 2);
            const float4 k4 = *reinterpret_cast<const float4*>(K + gi);
            const float4 v4 = *reinterpret_cast<const float4*>(V + gi);
            const int oo = (bh * Lsz + l) * 16 + e4;     // uint2 units in head-major scratch
            reinterpret_cast<uint2*>(g_Kh)[oo] = make_uint2(packh2(k4.x, k4.y), packh2(k4.z, k4.w));
            reinterpret_cast<uint2*>(g_Vh)[oo] = make_uint2(packh2(v4.x, v4.y), packh2(v4.z, v4.w));
        }
        __threadfence();
        __syncthreads();                             // all stores + fences done
        if (tid == 0) {
            const unsigned v = atomicAdd(&g_count[bh], 1u);   // arrival
            s_target = (v & ~3u) + 4u;               // this launch's completion count
        }
    }

    // ldmatrix lane addressing
    const int g  = lane >> 3, r8 = lane & 7;
    const unsigned qa_base = qs_u +
        (unsigned)(((wb + ((g & 1) << 3) + r8) * SKH + ((g >> 1) << 3)) * 2);
    const unsigned kf_off = (unsigned)(((((g >> 1) << 3) + r8) * SKH + ((g & 1) << 3)) * 2);
    const unsigned vf_off = (unsigned)(((((g & 1) << 3) + r8) * SKH + ((g >> 1) << 3)) * 2);

    // cp.async per-thread chunk mapping
    const int cp_row[2] = { tid >> 3, (256 + tid) >> 3 };        // rows 0..63
    const int cp_c8    = (tid & 7) * 8;

    // Perfectly balanced pairing: heavy tile (7-x) then light tile (x);
    // every block does (16-2x) + (2x+2) = 18 tile-units. 256 blocks = 1 wave.
    const int m0s[2] = { (7 - x) * BM, x * BM };

    #pragma unroll 1
    for (int phase = 0; phase < 2; ++phase) {
        const int m0 = m0s[phase];
        const bool has_diag = (m0 >= HIST);   // phase 0: true, phase 1: false

        // ---- Load Q (q_eff), pre-scaled by SCL2, fp16 (overlaps group wait) ----
        #pragma unroll
        for (int it = 0; it < 8; ++it) {
            const int idx = it * 256 + tid;
            const int r  = idx >> 4;
            const int ce = idx & 15;
            const int l  = m0 + r;
            const float* src = (l < HIST) ? Q : QD;
            const float4 v = *reinterpret_cast<const float4*>(src + base + l * rs + (ce << 2));
            *reinterpret_cast<uint2*>(Qh + r * SKH + (ce << 2)) =
                make_uint2(packh2(v.x * SCL2, v.y * SCL2), packh2(v.z * SCL2, v.w * SCL2));
        }
        // ---- Diagonal raw scores (full fp32, pre-scaled) ----
        if (has_diag && tid < BM) {
            const int l = m0 + tid;
            const float* qr = QD + base + l * rs;
            const float* kr = KD + base + l * rs;
            float acc = 0.f;
            #pragma unroll
            for (int ce = 0; ce < 16; ++ce) {
                const float4 qv = *reinterpret_cast<const float4*>(qr + (ce << 2));
                const float4 kv = *reinterpret_cast<const float4*>(kr + (ce << 2));
                acc += qv.x * kv.x + qv.y * kv.y + qv.z * kv.z + qv.w * kv.w;
            }
            dSs[tid] = acc * SCL2;
        }

        // ---- wait for all 4 blocks of this head to finish conversion ----
        if (phase == 0) {
            if (tid == 0) {
                const unsigned tgt = s_target;
                unsigned cur;
                do {
                    asm volatile("ld.acquire.gpu.u32 %0, [%1];"
                                 : "=r"(cur) : "l"(&g_count[bh]));
                } while ((int)(cur - tgt) < 0);
            }
        }

        const int ntiles = (m0 >> 6) + 2;

        // ---- prologue: issue cp.async for tiles 0 and 1 (stages 0, 1) ----
        __syncthreads();                      // Q + dSs + group-wait complete
        #pragma unroll
        for (int t0 = 0; t0 < 2; ++t0) {
            const unsigned sb = st_u[t0];
            #pragma unroll
            for (int it = 0; it < 2; ++it) {
                const int row = cp_row[it];
                const unsigned so = (unsigned)((row * SKH + cp_c8) * 2);
                const int go = (t0 * 64 + row) * Esz + cp_c8;
                cp16(sb + so,        kvK + go);
                cp16(sb + 9216 + so, kvV + go);
            }
            asm volatile("cp.async.commit_group;" ::: "memory");
        }

        // ---- Q A-fragments (persistent for this phase; 16 regs) ----
        unsigned qa[4][4];
        #pragma unroll
        for (int kb = 0; kb < 4; ++kb) ldsm4(qa[kb], qa_base + kb * 32);

        float o[8][4];
        #pragma unroll
        for (int nf = 0; nf < 8; ++nf)
            #pragma unroll
            for (int c = 0; c < 4; ++c) o[nf][c] = 0.f;
        float lsum0 = 0.f, lsum1 = 0.f;       // no-max softmax: P = 2^S

        const int l0 = m0 + wb + rr;
        const int l1 = l0 + 8;

        int stg = 0;
        for (int t = 0; t < ntiles; ++t) {
            asm volatile("cp.async.wait_group 1;" ::: "memory");
            __syncthreads();                  // tile t's stage visible; t-1 fully read

            // ---- issue cp.async for tile t+2 EARLY ----
            if (t + 2 < ntiles) {
                const int s2 = (stg + 2 >= 3) ? stg - 1 : stg + 2;
                const unsigned sb = st_u[s2];
                const int n2 = (t + 2) << 6;
                #pragma unroll
                for (int it = 0; it < 2; ++it) {
                    const int row = cp_row[it];
                    const unsigned so = (unsigned)((row * SKH + cp_c8) * 2);
                    const int go = (n2 + row) * Esz + cp_c8;
                    cp16(sb + so,        kvK + go);
                    cp16(sb + 9216 + so, kvV + go);
                }
            }
            asm volatile("cp.async.commit_group;" ::: "memory");

            const unsigned ks_b = st_u[stg];
            const unsigned vs_b = st_u[stg] + 9216;
            const int n0 = t << 6;
            const bool crossing = (n0 >= m0);
            const bool active = (wb + 15 + m0) >= n0;

            if (active) {
                // ---- S = Q @ K^T ----
                float s[8][4];
                #pragma unroll
                for (int nf = 0; nf < 8; ++nf)
                    #pragma unroll
                    for (int c = 0; c < 4; ++c) s[nf][c] = 0.f;
                #pragma unroll
                for (int kb = 0; kb < 4; ++kb) {
                    #pragma unroll
                    for (int nb = 0; nb < 4; ++nb) {
                        unsigned bb[4];
                        ldsm4(bb, ks_b + kf_off + (unsigned)((nb * 16 * SKH + kb * 16) * 2));
                        mma16816(s[2 * nb],     qa[kb], bb[0], bb[1]);
                        mma16816(s[2 * nb + 1], qa[kb], bb[2], bb[3]);
                    }
                }

                // ---- diag substitution + causal mask ----
                if (crossing) {
                    #pragma unroll
                    for (int nf = 0; nf < 8; ++nf) {
                        const int col = n0 + nf * 8 + 2 * qi;
                        if (has_diag) {
                            if (col     == l0) s[nf][0] = dSs[l0 - m0];
                            if (col + 1 == l0) s[nf][1] = dSs[l0 - m0];
                            if (col     == l1) s[nf][2] = dSs[l1 - m0];
                            if (col + 1 == l1) s[nf][3] = dSs[l1 - m0];
                        }
                        if (col     > l0) s[nf][0] = -INFINITY;
                        if (col + 1 > l0) s[nf][1] = -INFINITY;
                        if (col     > l1) s[nf][2] = -INFINITY;
                        if (col + 1 > l1) s[nf][3] = -INFINITY;
                    }
                }

                // ---- P = 2^S, packed ----
                unsigned ph[8][2];
                #pragma unroll
                for (int nf = 0; nf < 8; ++nf) {
                    ph[nf][0] = ex2h2(packh2(s[nf][0], s[nf][1]));
                    ph[nf][1] = ex2h2(packh2(s[nf][2], s[nf][3]));
                }

                // ---- capture diag probabilities (unnormalized) ----
                if (crossing && has_diag) {
                    #pragma unroll
                    for (int nf = 0; nf < 8; ++nf) {
                        const int col = n0 + nf * 8 + 2 * qi;
                        if (col     == l0) pdS[l0 - m0] = h2lo(ph[nf][0]);
                        if (col + 1 == l0) pdS[l0 - m0] = h2hi(ph[nf][0]);
                        if (col     == l1) pdS[l1 - m0] = h2lo(ph[nf][1]);
                        if (col + 1 == l1) pdS[l1 - m0] = h2hi(ph[nf][1]);
                    }
                }

                // ---- O += P @ V ; row sums via P @ ones ----
                float ssum[4] = {0.f, 0.f, 0.f, 0.f};
                #pragma unroll
                for (int kb = 0; kb < 4; ++kb) {
                    unsigned pa[4];
                    pa[0] = ph[2 * kb][0];
                    pa[1] = ph[2 * kb][1];
                    pa[2] = ph[2 * kb + 1][0];
                    pa[3] = ph[2 * kb + 1][1];
                    mma16816(ssum, pa, ONES2, ONES2);
                    #pragma unroll
                    for (int nb = 0; nb < 4; ++nb) {
                        unsigned bb[4];
                        ldsm4t(bb, vs_b + vf_off + (unsigned)((kb * 16 * SKH + nb * 16) * 2));
                        mma16816(o[2 * nb],     pa, bb[0], bb[1]);
                        mma16816(o[2 * nb + 1], pa, bb[2], bb[3]);
                    }
                }
                lsum0 += ssum[0];
                lsum1 += ssum[2];
            }

            stg = (stg + 1 == 3) ? 0 : stg + 1;
        }

        // ---- epilogue: diag value substitution, normalize, store ----
        __syncwarp();                        // pdS written by sibling lanes
        const float inv0 = 1.0f / lsum0;
        const float inv1 = 1.0f / lsum1;
        const float pd0 = has_diag ? pdS[l0 - m0] : 0.f;
        const float pd1 = has_diag ? pdS[l1 - m0] : 0.f;

        #pragma unroll
        for (int nf = 0; nf < 8; ++nf) {
            const int e = nf * 8 + 2 * qi;
            float v00 = o[nf][0], v01 = o[nf][1], v10 = o[nf][2], v11 = o[nf][3];
            if (has_diag) {
                const float2 vd0 = *reinterpret_cast<const float2*>(VD + base + l0 * rs + e);
                const float2 vo0 = *reinterpret_cast<const float2*>(V  + base + l0 * rs + e);
                const float2 vd1 = *reinterpret_cast<const float2*>(VD + base + l1 * rs + e);
                const float2 vo1 = *reinterpret_cast<const float2*>(V  + base + l1 * rs + e);
                v00 += pd0 * (vd0.x - vo0.x);
                v01 += pd0 * (vd0.y - vo0.y);
                v10 += pd1 * (vd1.x - vo1.x);
                v11 += pd1 * (vd1.y - vo1.y);
            }
            *reinterpret_cast<float2*>(Out + base + l0 * rs + e) = make_float2(v00 * inv0, v01 * inv0);
            *reinterpret_cast<float2*>(Out + base + l1 * rs + e) = make_float2(v10 * inv1, v11 * inv1);
        }

        // ---- phase transition: drain ring, then safe to restage Q/dSs ----
        if (phase == 0) {
            asm volatile("cp.async.wait_group 0;" ::: "memory");
            __syncthreads();
        }
    }
}

extern "C" void kernel_launch(void* const* d_in, const int* in_sizes, int n_in,
                              void* d_out, int out_size)
{
    const float* Q  = (const float*)d_in[0];
    const float* K  = (const float*)d_in[1];
    const float* V  = (const float*)d_in[2];
    const float* QD = (const float*)d_in[3];
    const float* KD = (const float*)d_in[4];
    const float* VD = (const float*)d_in[5];
    float* Out = (float*)d_out;

    cudaFuncSetAttribute(fftcc_attn_kernel,
                         cudaFuncAttributeMaxDynamicSharedMemorySize, SMEM_BYTES);
    dim3 grid(4, Bsz * Hsz);    // 256 blocks: one perfectly-balanced resident wave
    fftcc_attn_kernel<<<grid, 256, SMEM_BYTES>>>(Q, K, V, QD, KD, VD, Out);
}